// round 3
// baseline (speedup 1.0000x reference)
#include <cuda_runtime.h>
#include <cstdint>
#include <cstddef>

#define TS 2048
#define NB 256
#define BT (NB*TS)
typedef unsigned long long ull;

// ---------------- scratch (device globals: allocation-free) ----------------
__device__ float  g_states[(size_t)BT * 32];  // system_states (B,T,32)
__device__ float  g_combined[BT];             // 0.7*dr + 0.3*arrhenius
__device__ float4 g_phys[NB];                 // (Ea, logA, A, 0)

// ---------------- f32x2 helpers ----------------
__device__ __forceinline__ ull pk2(float x, float y) {
    ull r; asm("mov.b64 %0,{%1,%2};" : "=l"(r) : "f"(x), "f"(y)); return r;
}
__device__ __forceinline__ ull pkb(float x) { return pk2(x, x); }
__device__ __forceinline__ ull fma2(ull a, ull b, ull c) {
    ull d; asm("fma.rn.f32x2 %0,%1,%2,%3;" : "=l"(d) : "l"(a), "l"(b), "l"(c)); return d;
}
__device__ __forceinline__ float2 upk(ull v) {
    float lo, hi; asm("mov.b64 {%0,%1},%2;" : "=f"(lo), "=f"(hi) : "l"(v));
    return make_float2(lo, hi);
}

__device__ __forceinline__ float sigm(float x) {
    return __fdividef(1.f, 1.f + __expf(-x));
}
__device__ __forceinline__ float tanh_(float x) {
    return 1.f - __fdividef(2.f, __expf(2.f * x) + 1.f);
}

// ---------------- kernel A: physics branch (B=256 tiny MLP) ----------------
__global__ void phys_kernel(const float* __restrict__ sf,
                            const float* __restrict__ W1, const float* __restrict__ b1,
                            const float* __restrict__ W2, const float* __restrict__ b2,
                            const float* __restrict__ W3, const float* __restrict__ b3) {
    int b = threadIdx.x;
    if (b >= NB) return;
    float s0 = sf[b*3+0], s1 = sf[b*3+1], s2 = sf[b*3+2];
    float p1[32];
    #pragma unroll
    for (int j = 0; j < 32; j++) {
        float a = fmaf(W1[j*3+0], s0, fmaf(W1[j*3+1], s1, fmaf(W1[j*3+2], s2, b1[j])));
        p1[j] = fmaxf(a, 0.f);
    }
    float p2[16];
    #pragma unroll
    for (int j = 0; j < 16; j++) {
        float a = b2[j];
        #pragma unroll
        for (int k = 0; k < 32; k++) a = fmaf(W2[j*32+k], p1[k], a);
        p2[j] = fmaxf(a, 0.f);
    }
    float Ea = b3[0], lA = b3[1];
    #pragma unroll
    for (int k = 0; k < 16; k++) {
        Ea = fmaf(W3[k],      p2[k], Ea);
        lA = fmaf(W3[16 + k], p2[k], lA);
    }
    g_phys[b] = make_float4(Ea, lA, __expf(lA), 0.f);
}

// ---------------- kernel B: fused 2-layer LSTM + SE head ----------------
// 128 blocks (2 batches each), 128 threads: tid = b + 2*h.
// Lane-pairs share weight float4s (2 smem phases/LDS.128).
struct SB {
    float4 W0[66 * 64];    // [k*64+h], gates (i,f,g,o); k<2: Wih0, else Whh0
    float4 W1x[128 * 64];  // k<64: Wih1, else Whh1
    float4 B0[64], B1[64]; // combined biases
    float  SE1[64 * 32];   // [k*32+j] (se_W1 transposed)
    float  SE2[32 * 32];
    float  SEb1[32], SEb2[32];
    float  Hs1[2][2][68];  // [buf][b][k] (pad 68: 272B, 16B-aligned)
    float  Hs2[2][2][68];
    float  S1[32][2];
    float  Xs[2][2][2];    // [buf][d][b]
};

__global__ __launch_bounds__(128, 1)
void lstm_kernel(const float* __restrict__ ts,
                 const float* __restrict__ Wih0, const float* __restrict__ Whh0,
                 const float* __restrict__ bih0, const float* __restrict__ bhh0,
                 const float* __restrict__ Wih1, const float* __restrict__ Whh1,
                 const float* __restrict__ bih1, const float* __restrict__ bhh1,
                 const float* __restrict__ seW1, const float* __restrict__ seb1,
                 const float* __restrict__ seW2, const float* __restrict__ seb2) {
    extern __shared__ char smraw[];
    SB& S = *reinterpret_cast<SB*>(smraw);
    const int tid = threadIdx.x;
    const int b0  = blockIdx.x * 2;

    // ---- stage weights ----
    for (int idx = tid; idx < 66 * 64; idx += 128) {
        int h = idx & 63, k = idx >> 6; float4 w;
        if (k < 2) {
            w.x = Wih0[h*2+k];        w.y = Wih0[(64+h)*2+k];
            w.z = Wih0[(128+h)*2+k];  w.w = Wih0[(192+h)*2+k];
        } else {
            int kk = k - 2;
            w.x = Whh0[h*64+kk];       w.y = Whh0[(64+h)*64+kk];
            w.z = Whh0[(128+h)*64+kk]; w.w = Whh0[(192+h)*64+kk];
        }
        S.W0[idx] = w;
    }
    for (int idx = tid; idx < 128 * 64; idx += 128) {
        int h = idx & 63, k = idx >> 6; float4 w;
        if (k < 64) {
            w.x = Wih1[h*64+k];       w.y = Wih1[(64+h)*64+k];
            w.z = Wih1[(128+h)*64+k]; w.w = Wih1[(192+h)*64+k];
        } else {
            int kk = k - 64;
            w.x = Whh1[h*64+kk];       w.y = Whh1[(64+h)*64+kk];
            w.z = Whh1[(128+h)*64+kk]; w.w = Whh1[(192+h)*64+kk];
        }
        S.W1x[idx] = w;
    }
    if (tid < 64) {
        S.B0[tid] = make_float4(bih0[tid]+bhh0[tid],       bih0[64+tid]+bhh0[64+tid],
                                bih0[128+tid]+bhh0[128+tid], bih0[192+tid]+bhh0[192+tid]);
        S.B1[tid] = make_float4(bih1[tid]+bhh1[tid],       bih1[64+tid]+bhh1[64+tid],
                                bih1[128+tid]+bhh1[128+tid], bih1[192+tid]+bhh1[192+tid]);
    }
    for (int idx = tid; idx < 64 * 32; idx += 128) { int j = idx & 31, k = idx >> 5; S.SE1[idx] = seW1[j*64+k]; }
    for (int idx = tid; idx < 32 * 32; idx += 128) { int j = idx & 31, k = idx >> 5; S.SE2[idx] = seW2[j*32+k]; }
    if (tid < 32) { S.SEb1[tid] = seb1[tid]; S.SEb2[tid] = seb2[tid]; }
    for (int idx = tid; idx < 2 * 2 * 68; idx += 128) {
        ((float*)S.Hs1)[idx] = 0.f; ((float*)S.Hs2)[idx] = 0.f;
    }
    if (tid < 4) { int bi = tid & 1, d = tid >> 1; S.Xs[0][d][bi] = ts[((size_t)(b0+bi)*TS + 0)*2 + d]; }
    __syncthreads();

    const int b = tid & 1, h = tid >> 1;
    float c1 = 0.f, c2 = 0.f;
    const ulonglong2* W0u = (const ulonglong2*)S.W0;
    const ulonglong2* W1u = (const ulonglong2*)S.W1x;
    float4 bb0 = S.B0[h], bb1 = S.B1[h];
    const ull bias01 = pk2(bb0.x, bb0.y), bias02 = pk2(bb0.z, bb0.w);
    const ull bias11 = pk2(bb1.x, bb1.y), bias12 = pk2(bb1.z, bb1.w);

    for (int t = 0; t < TS; t++) {
        const int cur = t & 1, nxt = cur ^ 1;
        if (tid < 4 && t + 1 < TS) {
            int bi = tid & 1, d = tid >> 1;
            S.Xs[nxt][d][bi] = ts[((size_t)(b0+bi)*TS + (t+1))*2 + d];
        }
        // -------- layer 0 --------
        ull a1 = bias01, a2 = bias02;
        {
            ull xx0 = pkb(S.Xs[cur][0][b]), xx1 = pkb(S.Xs[cur][1][b]);
            ulonglong2 w0 = W0u[h], w1 = W0u[64 + h];
            a1 = fma2(w0.x, xx0, a1); a2 = fma2(w0.y, xx0, a2);
            a1 = fma2(w1.x, xx1, a1); a2 = fma2(w1.y, xx1, a2);
        }
        #pragma unroll
        for (int k4 = 0; k4 < 64; k4 += 4) {
            float4 hv = *(const float4*)&S.Hs1[cur][b][k4];
            ulonglong2 w; ull x;
            w = W0u[(2+k4)*64+h]; x = pkb(hv.x); a1 = fma2(w.x, x, a1); a2 = fma2(w.y, x, a2);
            w = W0u[(3+k4)*64+h]; x = pkb(hv.y); a1 = fma2(w.x, x, a1); a2 = fma2(w.y, x, a2);
            w = W0u[(4+k4)*64+h]; x = pkb(hv.z); a1 = fma2(w.x, x, a1); a2 = fma2(w.y, x, a2);
            w = W0u[(5+k4)*64+h]; x = pkb(hv.w); a1 = fma2(w.x, x, a1); a2 = fma2(w.y, x, a2);
        }
        {
            float2 pif = upk(a1), pgo = upk(a2);
            float gi = sigm(pif.x), gf = sigm(pif.y), gg = tanh_(pgo.x), go = sigm(pgo.y);
            c1 = gf * c1 + gi * gg;
            S.Hs1[nxt][b][h] = go * tanh_(c1);
        }
        __syncthreads();
        // -------- layer 1 --------
        a1 = bias11; a2 = bias12;
        #pragma unroll
        for (int k4 = 0; k4 < 64; k4 += 4) {
            float4 hv = *(const float4*)&S.Hs1[nxt][b][k4];
            ulonglong2 w; ull x;
            w = W1u[(k4+0)*64+h]; x = pkb(hv.x); a1 = fma2(w.x, x, a1); a2 = fma2(w.y, x, a2);
            w = W1u[(k4+1)*64+h]; x = pkb(hv.y); a1 = fma2(w.x, x, a1); a2 = fma2(w.y, x, a2);
            w = W1u[(k4+2)*64+h]; x = pkb(hv.z); a1 = fma2(w.x, x, a1); a2 = fma2(w.y, x, a2);
            w = W1u[(k4+3)*64+h]; x = pkb(hv.w); a1 = fma2(w.x, x, a1); a2 = fma2(w.y, x, a2);
        }
        #pragma unroll
        for (int k4 = 0; k4 < 64; k4 += 4) {
            float4 hv = *(const float4*)&S.Hs2[cur][b][k4];
            ulonglong2 w; ull x;
            w = W1u[(64+k4+0)*64+h]; x = pkb(hv.x); a1 = fma2(w.x, x, a1); a2 = fma2(w.y, x, a2);
            w = W1u[(64+k4+1)*64+h]; x = pkb(hv.y); a1 = fma2(w.x, x, a1); a2 = fma2(w.y, x, a2);
            w = W1u[(64+k4+2)*64+h]; x = pkb(hv.z); a1 = fma2(w.x, x, a1); a2 = fma2(w.y, x, a2);
            w = W1u[(64+k4+3)*64+h]; x = pkb(hv.w); a1 = fma2(w.x, x, a1); a2 = fma2(w.y, x, a2);
        }
        {
            float2 pif = upk(a1), pgo = upk(a2);
            float gi = sigm(pif.x), gf = sigm(pif.y), gg = tanh_(pgo.x), go = sigm(pgo.y);
            c2 = gf * c2 + gi * gg;
            S.Hs2[nxt][b][h] = go * tanh_(c2);
        }
        __syncthreads();
        // -------- SE head: states = W2 @ relu(W1 @ h2 + b1) + b2 --------
        if (tid < 64) {
            int j = tid >> 1, bb = tid & 1;
            float acc = S.SEb1[j];
            #pragma unroll 16
            for (int k = 0; k < 64; k++) acc = fmaf(S.SE1[k*32+j], S.Hs2[nxt][bb][k], acc);
            S.S1[j][bb] = fmaxf(acc, 0.f);
        }
        __syncthreads();
        if (tid < 64) {
            int j = tid >> 1, bb = tid & 1;
            float acc = S.SEb2[j];
            #pragma unroll
            for (int k = 0; k < 32; k++) acc = fmaf(S.SE2[k*32+j], S.S1[k][bb], acc);
            g_states[((size_t)(b0+bb)*TS + t)*32 + j] = acc;
        }
        // no sync needed here: next-iter writes are all barrier-separated
    }
}

// ---------------- kernel C: degradation-rate MLP + arrhenius ----------------
__global__ __launch_bounds__(256)
void dr_kernel(const float* __restrict__ ts,
               const float* __restrict__ W1, const float* __restrict__ b1,
               const float* __restrict__ W2, const float* __restrict__ b2,
               const float* __restrict__ W3, const float* __restrict__ b3,
               float* __restrict__ out) {
    __shared__ float sW1[64*35], sb1[64], sW2[32*64], sb2[32], sW3[32], sb3[1];
    int tid = threadIdx.x;
    for (int i = tid; i < 64*35; i += 256) sW1[i] = W1[i];
    for (int i = tid; i < 32*64; i += 256) sW2[i] = W2[i];
    if (tid < 64) sb1[tid] = b1[tid];
    if (tid < 32) { sb2[tid] = b2[tid]; sW3[tid] = W3[tid]; }
    if (tid == 0) sb3[0] = b3[0];
    __syncthreads();

    size_t p = (size_t)blockIdx.x * 256 + tid;
    int b = (int)(p >> 11);
    float in[35];
    const float* st = &g_states[p * 32];
    #pragma unroll
    for (int i = 0; i < 32; i += 4) {
        float4 v = *(const float4*)&st[i];
        in[i] = v.x; in[i+1] = v.y; in[i+2] = v.z; in[i+3] = v.w;
    }
    float temp = ts[p * 2];
    float4 ph = g_phys[b];
    in[32] = temp; in[33] = ph.x; in[34] = ph.y;

    float h1[64];
    #pragma unroll
    for (int j = 0; j < 64; j++) {
        float a = sb1[j];
        #pragma unroll
        for (int k = 0; k < 35; k++) a = fmaf(sW1[j*35+k], in[k], a);
        h1[j] = fmaxf(a, 0.f);
    }
    float dr = sb3[0];
    #pragma unroll
    for (int j = 0; j < 32; j++) {
        float a = sb2[j];
        #pragma unroll
        for (int k = 0; k < 64; k++) a = fmaf(sW2[j*64+k], h1[k], a);
        dr = fmaf(sW3[j], fmaxf(a, 0.f), dr);
    }
    float arr = ph.z * __expf(-ph.x * 1000.f / (8.314f * (temp + 273.15f)));
    out[(size_t)BT + p] = dr;
    g_combined[p] = fmaf(0.7f, dr, 0.3f * arr);
}

// ---------------- kernel D: health scan (clamp-composition warp scan) -------
// f_c(x) = clamp(x - c, 0, 1); compositions stay clamp(x+s, L, U).
__global__ void scan_kernel(float* __restrict__ out) {
    int batch = blockIdx.x * 2 + (threadIdx.x >> 5);
    int lane  = threadIdx.x & 31;
    const float* cb = &g_combined[(size_t)batch * TS];
    float* hb = &out[(size_t)2 * BT + (size_t)batch * TS];
    float carry = 1.f;
    for (int ch = 0; ch < TS; ch += 32) {
        float c = cb[ch + lane];
        float s = -c, L = 0.f, U = 1.f;
        #pragma unroll
        for (int d = 1; d < 32; d <<= 1) {
            float ps = __shfl_up_sync(0xffffffffu, s, d);
            float pL = __shfl_up_sync(0xffffffffu, L, d);
            float pU = __shfl_up_sync(0xffffffffu, U, d);
            if (lane >= d) {   // self ∘ prev
                float ns = ps + s;
                float nL = fminf(fmaxf(pL + s, L), U);
                float nU = fminf(fmaxf(pU + s, L), U);
                s = ns; L = nL; U = nU;
            }
        }
        float hv = fminf(fmaxf(carry + s, L), U);
        hb[ch + lane] = hv;
        carry = __shfl_sync(0xffffffffu, hv, 31);
    }
}

// ---------------- kernel E: RUL head ----------------
__global__ __launch_bounds__(256)
void rul_kernel(const float* __restrict__ W1, const float* __restrict__ b1,
                const float* __restrict__ W2, const float* __restrict__ b2,
                float* __restrict__ out) {
    __shared__ float sW1[32*33], sb1[32], sW2[32], sb2s[1];
    int tid = threadIdx.x;
    for (int i = tid; i < 32*33; i += 256) sW1[i] = W1[i];
    if (tid < 32) { sb1[tid] = b1[tid]; sW2[tid] = W2[tid]; }
    if (tid == 0) sb2s[0] = b2[0];
    __syncthreads();

    size_t p = (size_t)blockIdx.x * 256 + tid;
    const float* st = &g_states[p * 32];
    float stv[32];
    #pragma unroll
    for (int i = 0; i < 32; i += 4) {
        float4 v = *(const float4*)&st[i];
        stv[i] = v.x; stv[i+1] = v.y; stv[i+2] = v.z; stv[i+3] = v.w;
    }
    float hv = out[(size_t)2 * BT + p];
    float r = sb2s[0];
    #pragma unroll
    for (int j = 0; j < 32; j++) {
        float a = sb1[j];
        #pragma unroll
        for (int k = 0; k < 32; k++) a = fmaf(sW1[j*33+k], stv[k], a);
        a = fmaf(sW1[j*33+32], hv, a);
        r = fmaf(sW2[j], fmaxf(a, 0.f), r);
    }
    out[p] = fmaxf(r, 0.f);
}

// ---------------- launch ----------------
extern "C" void kernel_launch(void* const* d_in, const int* in_sizes, int n_in,
                              void* d_out, int out_size) {
    const float* ts = (const float*)d_in[0];
    const float* sf = (const float*)d_in[1];
    float* out = (float*)d_out;

    cudaFuncSetAttribute(lstm_kernel, cudaFuncAttributeMaxDynamicSharedMemorySize,
                         (int)sizeof(SB));

    phys_kernel<<<1, 256>>>(sf,
        (const float*)d_in[14], (const float*)d_in[15],
        (const float*)d_in[16], (const float*)d_in[17],
        (const float*)d_in[18], (const float*)d_in[19]);

    lstm_kernel<<<128, 128, sizeof(SB)>>>(ts,
        (const float*)d_in[2],  (const float*)d_in[3],
        (const float*)d_in[4],  (const float*)d_in[5],
        (const float*)d_in[6],  (const float*)d_in[7],
        (const float*)d_in[8],  (const float*)d_in[9],
        (const float*)d_in[10], (const float*)d_in[11],
        (const float*)d_in[12], (const float*)d_in[13]);

    dr_kernel<<<BT/256, 256>>>(ts,
        (const float*)d_in[20], (const float*)d_in[21],
        (const float*)d_in[22], (const float*)d_in[23],
        (const float*)d_in[24], (const float*)d_in[25], out);

    scan_kernel<<<128, 64>>>(out);

    rul_kernel<<<BT/256, 256>>>(
        (const float*)d_in[26], (const float*)d_in[27],
        (const float*)d_in[28], (const float*)d_in[29], out);
}